// round 13
// baseline (speedup 1.0000x reference)
#include <cuda_runtime.h>
#include <cuda_bf16.h>
#include <cstdint>

#define NRANGES 256
#define KPR     512
#define DOP     64
#define EMB     16
#define FIN     96
#define NTOT    (NRANGES * KPR)

// ---- proj config: 128 threads, 64 rows/CTA, HMMA ----
#define PROJ_THREADS 128
#define PROJ_ROWS    64
#define PSTR         52                  // smem row stride in words (96 bf16 -> 52w pad)
#define P_BIAS 0                         // 136 floats  [bq|bk|bvs|0..]
#define P_WV   136                       // 96 floats   wv colsums
#define P_XH   232                       // 64*52 words
#define P_XL   (P_XH + 64*PSTR)
#define P_BH   (P_XL + 64*PSTR)          // 136*52 words
#define P_BL   (P_BH + 136*PSTR)
#define P_WORDS (P_BL + 136*PSTR)        // 21032 words = 84128 B

// ---- attn config ----
#define ATTN_THREADS 512                 // 16 warps x 32 q-rows
#define KROW_STRIDE  144                 // 36 words; conflict-free B frags
#define SM_VS        0
#define SM_KH        2048
#define SM_KL        (SM_KH + KPR * KROW_STRIDE)
#define SM_ATTN      (SM_KL + KPR * KROW_STRIDE)   // 149504 B

// Q pre-scale: 1/sqrt(64) applied as 1/8, fused with log2(e) for ex2-softmax
#define QSCALE 0.18033688011112042f      // 0.125 * log2(e)

// ---- global scratch (allocation-free rule) ----
__device__ __align__(256) __nv_bfloat16 g_Qh[(size_t)NTOT * DOP];
__device__ __align__(256) __nv_bfloat16 g_Ql[(size_t)NTOT * DOP];
__device__ __align__(256) __nv_bfloat16 g_Kh[(size_t)NTOT * DOP];
__device__ __align__(256) __nv_bfloat16 g_Kl[(size_t)NTOT * DOP];
__device__ __align__(256) float         g_vs[NTOT];

// ---- helpers ----
#define MMA16816(C, A, B) \
    asm volatile("mma.sync.aligned.m16n8k16.row.col.f32.bf16.bf16.f32 " \
                 "{%0,%1,%2,%3}, {%4,%5,%6,%7}, {%8,%9}, {%0,%1,%2,%3};" \
                 : "+f"((C)[0]), "+f"((C)[1]), "+f"((C)[2]), "+f"((C)[3]) \
                 : "r"((A)[0]), "r"((A)[1]), "r"((A)[2]), "r"((A)[3]), \
                   "r"((B)[0]), "r"((B)[1]))

__device__ __forceinline__ float ex2f(float x) {
    float r; asm("ex2.approx.f32 %0, %1;" : "=f"(r) : "f"(x)); return r;
}

// trunc-split a pair of fp32 into packed bf16 hi (prmt) + bf16 lo (exact residual, rn)
__device__ __forceinline__ void split_pair(float v0, float v1,
                                           uint32_t& h, uint32_t& l) {
    uint32_t x0 = __float_as_uint(v0), x1 = __float_as_uint(v1);
    asm("prmt.b32 %0, %1, %2, 0x7632;" : "=r"(h) : "r"(x0), "r"(x1));
    float h0 = __uint_as_float(x0 & 0xFFFF0000u);
    float h1 = __uint_as_float(x1 & 0xFFFF0000u);
    float l0 = v0 - h0, l1 = v1 - h1;
    asm("cvt.rn.bf16x2.f32 %0, %1, %2;" : "=r"(l) : "f"(l1), "f"(l0));
}

// ---------------------------------------------------------------------------
// Kernel 1: HMMA projection. C[64 rows][136 cols] = X[64][96] * B'[96][136]^T
//   B' rows (n): 0..63 Wq, 64..127 Wk, 128 wv_colsum (vsum as a GEMM column!),
//   129..135 zero. Epilogue: +bias, Q*=QSCALE, trunc-split to bf16 hi/lo.
// ---------------------------------------------------------------------------
__global__ void __launch_bounds__(PROJ_THREADS)
proj_kernel(const float* __restrict__ pv,
            const int*   __restrict__ ele,
            const int*   __restrict__ azi,
            const float* __restrict__ ele_t,
            const float* __restrict__ azi_t,
            const float* __restrict__ Wq, const float* __restrict__ bq,
            const float* __restrict__ Wk, const float* __restrict__ bk,
            const float* __restrict__ Wv, const float* __restrict__ bv)
{
    extern __shared__ float sm[];
    float*    sbias = sm + P_BIAS;
    float*    swv   = sm + P_WV;
    uint32_t* sXh   = (uint32_t*)sm + P_XH;
    uint32_t* sXl   = (uint32_t*)sm + P_XL;
    uint32_t* sBh   = (uint32_t*)sm + P_BH;
    uint32_t* sBl   = (uint32_t*)sm + P_BL;

    const int tid = threadIdx.x;
    const int n0  = blockIdx.x * PROJ_ROWS;

    // ---- stage 1a: bias + wv colsums ----
    if (tid < 64)       sbias[tid] = bq[tid];
    else if (tid < 128) sbias[tid] = bk[tid - 64];
    if (tid < FIN) {
        float s0 = 0.f, s1 = 0.f, s2 = 0.f, s3 = 0.f;
        #pragma unroll 4
        for (int d = 0; d < DOP; d += 4) {
            s0 += Wv[(d+0) * FIN + tid];
            s1 += Wv[(d+1) * FIN + tid];
            s2 += Wv[(d+2) * FIN + tid];
            s3 += Wv[(d+3) * FIN + tid];
        }
        swv[tid] = (s0 + s1) + (s2 + s3);
    }
    if (tid == 0) {
        float s = 0.f;
        for (int d = 0; d < DOP; ++d) s += bv[d];
        sbias[128] = s;
    }
    if (tid >= 1 && tid < 8) sbias[128 + tid] = 0.f;

    // ---- stage 1b: W rows 0..127 -> bf16 hi/lo ----
    for (int i = tid; i < 128 * 48; i += PROJ_THREADS) {
        int n = i / 48, w = i - n * 48;
        float2 v = (n < 64) ? *(const float2*)(Wq + n * FIN + 2 * w)
                            : *(const float2*)(Wk + (n - 64) * FIN + 2 * w);
        split_pair(v.x, v.y, sBh[n * PSTR + w], sBl[n * PSTR + w]);
    }

    // ---- stage 1c: X gather + split (2 threads per row) ----
    {
        const int row = tid >> 1, half = tid & 1;
        const int n = n0 + row;
        uint32_t* xh = sXh + row * PSTR;
        uint32_t* xl = sXl + row * PSTR;
        if (half == 0) {
            const float4* p4 = (const float4*)(pv + (size_t)n * DOP);
            #pragma unroll
            for (int j = 0; j < 12; ++j) {
                float4 v = p4[j];
                split_pair(v.x, v.y, xh[2*j],   xl[2*j]);
                split_pair(v.z, v.w, xh[2*j+1], xl[2*j+1]);
            }
        } else {
            const float4* p4 = (const float4*)(pv + (size_t)n * DOP);
            #pragma unroll
            for (int j = 12; j < 16; ++j) {
                float4 v = p4[j];
                split_pair(v.x, v.y, xh[2*j],   xl[2*j]);
                split_pair(v.z, v.w, xh[2*j+1], xl[2*j+1]);
            }
            const int ei = ele[n], ai = azi[n];
            const float4* e4 = (const float4*)(ele_t + ei * EMB);
            const float4* a4 = (const float4*)(azi_t + ai * EMB);
            #pragma unroll
            for (int j = 0; j < 4; ++j) {
                float4 v = e4[j];
                split_pair(v.x, v.y, xh[32 + 2*j],   xl[32 + 2*j]);
                split_pair(v.z, v.w, xh[32 + 2*j+1], xl[32 + 2*j+1]);
                float4 w = a4[j];
                split_pair(w.x, w.y, xh[40 + 2*j],   xl[40 + 2*j]);
                split_pair(w.z, w.w, xh[40 + 2*j+1], xl[40 + 2*j+1]);
            }
        }
    }
    __syncthreads();

    // ---- stage 2: B rows 128..135 (wv column + zero pad) ----
    for (int i = tid; i < 8 * 48; i += PROJ_THREADS) {
        int n = 128 + i / 48, w = i % 48;
        uint32_t h = 0, l = 0;
        if (n == 128) split_pair(swv[2*w], swv[2*w + 1], h, l);
        sBh[n * PSTR + w] = h;
        sBl[n * PSTR + w] = l;
    }
    __syncthreads();

    // ---- MMA phase: warp owns 16 rows ----
    const int wid  = tid >> 5;
    const int lane = tid & 31;
    const int g    = lane >> 2;
    const int t    = lane & 3;
    const int nw   = wid * 16;
    const int gr0  = n0 + nw;
    const int r0   = gr0 + g, r1 = r0 + 8;

    // A fragments (persist): 6 k-steps, hi+lo
    uint32_t ah[6][4], al[6][4];
    {
        const uint32_t* x0h = sXh + (nw + g) * PSTR + t;
        const uint32_t* x1h = x0h + 8 * PSTR;
        const uint32_t* x0l = sXl + (nw + g) * PSTR + t;
        const uint32_t* x1l = x0l + 8 * PSTR;
        #pragma unroll
        for (int ks = 0; ks < 6; ++ks) {
            ah[ks][0] = x0h[8*ks];     ah[ks][1] = x1h[8*ks];
            ah[ks][2] = x0h[8*ks + 4]; ah[ks][3] = x1h[8*ks + 4];
            al[ks][0] = x0l[8*ks];     al[ks][1] = x1l[8*ks];
            al[ks][2] = x0l[8*ks + 4]; al[ks][3] = x1l[8*ks + 4];
        }
    }

    uint32_t* qhw = (uint32_t*)g_Qh;
    uint32_t* qlw = (uint32_t*)g_Ql;
    uint32_t* khw = (uint32_t*)g_Kh;
    uint32_t* klw = (uint32_t*)g_Kl;

    #pragma unroll 2
    for (int nbp = 0; nbp < 8; ++nbp) {
        const int nb0 = 2 * nbp, nb1 = nb0 + 1;
        const uint32_t* B0 = sBh + (8 * nb0 + g) * PSTR + t;
        const uint32_t* B1 = sBh + (8 * nb1 + g) * PSTR + t;
        uint32_t b0[6][2], b1[6][2];
        #pragma unroll
        for (int ks = 0; ks < 6; ++ks) {
            b0[ks][0] = B0[8*ks]; b0[ks][1] = B0[8*ks + 4];
            b1[ks][0] = B1[8*ks]; b1[ks][1] = B1[8*ks + 4];
        }
        float Ca0[4] = {0,0,0,0}, Ca1[4] = {0,0,0,0};
        float Cb0[4] = {0,0,0,0}, Cb1[4] = {0,0,0,0};
        #pragma unroll
        for (int ks = 0; ks < 6; ++ks) {
            MMA16816(Ca0, ah[ks], b0[ks]);
            MMA16816(Ca1, ah[ks], b1[ks]);
            MMA16816(Cb0, al[ks], b0[ks]);
            MMA16816(Cb1, al[ks], b1[ks]);
        }
        const uint32_t* B0l = sBl + (8 * nb0 + g) * PSTR + t;
        const uint32_t* B1l = sBl + (8 * nb1 + g) * PSTR + t;
        #pragma unroll
        for (int ks = 0; ks < 6; ++ks) {
            b0[ks][0] = B0l[8*ks]; b0[ks][1] = B0l[8*ks + 4];
            b1[ks][0] = B1l[8*ks]; b1[ks][1] = B1l[8*ks + 4];
        }
        #pragma unroll
        for (int ks = 0; ks < 6; ++ks) {
            MMA16816(Ca0, ah[ks], b0[ks]);
            MMA16816(Ca1, ah[ks], b1[ks]);
        }

        // ---- epilogue for nb0, nb1 ----
        #pragma unroll
        for (int e = 0; e < 2; ++e) {
            const int nb = e ? nb1 : nb0;
            const float* Ca = e ? Ca1 : Ca0;
            const float* Cb = e ? Cb1 : Cb0;
            const int c0 = 8 * nb + 2 * t;
            const bool isQ = (nb < 8);
            const float sc = isQ ? QSCALE : 1.0f;
            uint32_t* dh = isQ ? qhw : khw;
            uint32_t* dl = isQ ? qlw : klw;
            const int cw = isQ ? (4 * nb + t) : (4 * (nb - 8) + t);
            const float bb0 = sbias[c0], bb1 = sbias[c0 + 1];
            float v00 = (Ca[0] + Cb[0] + bb0) * sc;
            float v01 = (Ca[1] + Cb[1] + bb1) * sc;
            float v10 = (Ca[2] + Cb[2] + bb0) * sc;
            float v11 = (Ca[3] + Cb[3] + bb1) * sc;
            uint32_t h, l;
            split_pair(v00, v01, h, l);
            dh[(size_t)r0 * 32 + cw] = h; dl[(size_t)r0 * 32 + cw] = l;
            split_pair(v10, v11, h, l);
            dh[(size_t)r1 * 32 + cw] = h; dl[(size_t)r1 * 32 + cw] = l;
        }
    }

    // ---- tail n-block 16: vsum column ----
    {
        const uint32_t* B0 = sBh + (128 + g) * PSTR + t;
        uint32_t b0[6][2];
        #pragma unroll
        for (int ks = 0; ks < 6; ++ks) {
            b0[ks][0] = B0[8*ks]; b0[ks][1] = B0[8*ks + 4];
        }
        float Ca[4] = {0,0,0,0}, Cb[4] = {0,0,0,0};
        #pragma unroll
        for (int ks = 0; ks < 6; ++ks) {
            MMA16816(Ca, ah[ks], b0[ks]);
            MMA16816(Cb, al[ks], b0[ks]);
        }
        const uint32_t* B0l = sBl + (128 + g) * PSTR + t;
        #pragma unroll
        for (int ks = 0; ks < 6; ++ks) {
            b0[ks][0] = B0l[8*ks]; b0[ks][1] = B0l[8*ks + 4];
        }
        #pragma unroll
        for (int ks = 0; ks < 6; ++ks) MMA16816(Ca, ah[ks], b0[ks]);
        if (t == 0) {
            const float bvs = sbias[128];
            g_vs[r0] = Ca[0] + Cb[0] + bvs;
            g_vs[r1] = Ca[2] + Cb[2] + bvs;
        }
    }
}

// ---------------------------------------------------------------------------
// Kernel 2: HMMA attention, 16 keys/iter, 4 independent C chains per warp.
//   S = Qh.Kh^T + Ql.Kh^T + Qh.Kl^T (fp32 accum); p = ex2(S) (log2e folded
//   into Q scale); out = sum(p*vs)/sum(p).
// ---------------------------------------------------------------------------
__global__ void __launch_bounds__(ATTN_THREADS, 1)
attn_kernel(float* __restrict__ out)
{
    extern __shared__ char smem[];
    float* vsm = (float*)(smem + SM_VS);

    const int tid  = threadIdx.x;
    const int wid  = tid >> 5;
    const int lane = tid & 31;
    const int g    = lane >> 2;
    const int t    = lane & 3;
    const int r    = blockIdx.x;

    // ---- stage K hi/lo + vs ----
    {
        const uint4* khg = (const uint4*)(g_Kh + (size_t)r * KPR * DOP);
        const uint4* klg = (const uint4*)(g_Kl + (size_t)r * KPR * DOP);
        for (int i = tid; i < KPR * 8; i += ATTN_THREADS) {
            int row = i >> 3, c = i & 7;
            *(uint4*)(smem + SM_KH + row * KROW_STRIDE + c * 16) = khg[i];
            *(uint4*)(smem + SM_KL + row * KROW_STRIDE + c * 16) = klg[i];
        }
        if (tid < KPR) vsm[tid] = g_vs[r * KPR + tid];
    }
    __syncthreads();

    // ---- Q fragments (persist), straight from gmem ----
    const int m0 = wid * 32;
    const uint32_t* qhg = (const uint32_t*)g_Qh + ((size_t)r * KPR + m0) * 32;
    const uint32_t* qlg = (const uint32_t*)g_Ql + ((size_t)r * KPR + m0) * 32;
    uint32_t qh[2][4][4], ql[2][4][4];
    #pragma unroll
    for (int mt = 0; mt < 2; ++mt) {
        const int row0 = mt * 16 + g;
        #pragma unroll
        for (int ks = 0; ks < 4; ++ks) {
            const int w0 = 8 * ks + t, w1 = w0 + 4;
            qh[mt][ks][0] = qhg[row0 * 32 + w0];
            qh[mt][ks][1] = qhg[(row0 + 8) * 32 + w0];
            qh[mt][ks][2] = qhg[row0 * 32 + w1];
            qh[mt][ks][3] = qhg[(row0 + 8) * 32 + w1];
            ql[mt][ks][0] = qlg[row0 * 32 + w0];
            ql[mt][ks][1] = qlg[(row0 + 8) * 32 + w0];
            ql[mt][ks][2] = qlg[row0 * 32 + w1];
            ql[mt][ks][3] = qlg[(row0 + 8) * 32 + w1];
        }
    }

    float num[4] = {0.f, 0.f, 0.f, 0.f};
    float den[4] = {0.f, 0.f, 0.f, 0.f};

    #pragma unroll 1
    for (int nb = 0; nb < KPR / 16; ++nb) {
        const int n0 = nb * 16;
        const char* rh = smem + SM_KH + (n0 + g) * KROW_STRIDE + t * 4;
        uint32_t b0[4][2], b1[4][2];
        #pragma unroll
        for (int ks = 0; ks < 4; ++ks) {
            b0[ks][0] = *(const uint32_t*)(rh + ks * 32);
            b0[ks][1] = *(const uint32_t*)(rh + ks * 32 + 16);
            b1[ks][0] = *(const uint32_t*)(rh + 8 * KROW_STRIDE + ks * 32);
            b1[ks][1] = *(const uint32_t*)(rh + 8 * KROW_STRIDE + ks * 32 + 16);
        }

        float C00[4] = {0,0,0,0}, C01[4] = {0,0,0,0};
        float C10[4] = {0,0,0,0}, C11[4] = {0,0,0,0};
        #pragma unroll
        for (int ks = 0; ks < 4; ++ks) {
            MMA16816(C00, qh[0][ks], b0[ks]);
            MMA16816(C01, qh[0][ks], b1[ks]);
            MMA16816(C10, qh[1][ks], b0[ks]);
            MMA16816(C11, qh[1][ks], b1[ks]);
        }
        #pragma unroll
        for (int ks = 0; ks < 4; ++ks) {
            MMA16816(C00, ql[0][ks], b0[ks]);
            MMA16816(C01, ql[0][ks], b1[ks]);
            MMA16816(C10, ql[1][ks], b0[ks]);
            MMA16816(C11, ql[1][ks], b1[ks]);
        }
        const char* rl = smem + SM_KL + (n0 + g) * KROW_STRIDE + t * 4;
        #pragma unroll
        for (int ks = 0; ks < 4; ++ks) {
            b0[ks][0] = *(const uint32_t*)(rl + ks * 32);
            b0[ks][1] = *(const uint32_t*)(rl + ks * 32 + 16);
            b1[ks][0] = *(const uint32_t*)(rl + 8 * KROW_STRIDE + ks * 32);
            b1[ks][1] = *(const uint32_t*)(rl + 8 * KROW_STRIDE + ks * 32 + 16);
        }
        #pragma unroll
        for (int ks = 0; ks < 4; ++ks) {
            MMA16816(C00, qh[0][ks], b0[ks]);
            MMA16816(C01, qh[0][ks], b1[ks]);
            MMA16816(C10, qh[1][ks], b0[ks]);
            MMA16816(C11, qh[1][ks], b1[ks]);
        }

        // ---- epilogue: 16 ex2 per thread ----
        const float2 v0 = *(const float2*)(vsm + n0 + 2 * t);
        const float2 v1 = *(const float2*)(vsm + n0 + 8 + 2 * t);
        {
            float p0 = ex2f(C00[0]), p1 = ex2f(C00[1]);
            float p2 = ex2f(C01[0]), p3 = ex2f(C01[1]);
            den[0] += (p0 + p1) + (p2 + p3);
            num[0] = fmaf(p0, v0.x, fmaf(p1, v0.y,
                     fmaf(p2, v1.x, fmaf(p3, v1.y, num[0]))));
            p0 = ex2f(C00[2]); p1 = ex2f(C00[3]);
            p2 = ex2f(C01[2]); p3 = ex2f(C01[3]);
            den[1] += (p0 + p1) + (p2 + p3);
            num[1] = fmaf(p0, v0.x, fmaf(p1, v0.y,
                     fmaf(p2, v1.x, fmaf(p3, v1.y, num[1]))));
            p0 = ex2f(C10[0]); p1 = ex2f(C10[1]);
            p2 = ex2f(C11[0]); p3 = ex2f(C11[1]);
            den[2] += (p0 + p1) + (p2 + p3);
            num[2] = fmaf(p0, v0.x, fmaf(p1, v0.y,
                     fmaf(p2, v1.x, fmaf(p3, v1.y, num[2]))));
            p0 = ex2f(C10[2]); p1 = ex2f(C10[3]);
            p2 = ex2f(C11[2]); p3 = ex2f(C11[3]);
            den[3] += (p0 + p1) + (p2 + p3);
            num[3] = fmaf(p0, v0.x, fmaf(p1, v0.y,
                     fmaf(p2, v1.x, fmaf(p3, v1.y, num[3]))));
        }
    }

    // quad reduction across t
    #pragma unroll
    for (int j = 0; j < 4; ++j) {
        num[j] += __shfl_xor_sync(0xffffffffu, num[j], 1);
        den[j] += __shfl_xor_sync(0xffffffffu, den[j], 1);
        num[j] += __shfl_xor_sync(0xffffffffu, num[j], 2);
        den[j] += __shfl_xor_sync(0xffffffffu, den[j], 2);
    }
    if (t == 0) {
        #pragma unroll
        for (int mt = 0; mt < 2; ++mt) {
            out[r * KPR + m0 + mt * 16 + g]     = num[2*mt]   / den[2*mt];
            out[r * KPR + m0 + mt * 16 + 8 + g] = num[2*mt+1] / den[2*mt+1];
        }
    }
}

// ---------------------------------------------------------------------------
extern "C" void kernel_launch(void* const* d_in, const int* in_sizes, int n_in,
                              void* d_out, int out_size)
{
    const float* pv    = (const float*)d_in[0];
    const int*   ele   = (const int*)  d_in[1];
    // d_in[2] = range_indices: unused by the reference computation
    const int*   azi   = (const int*)  d_in[3];
    const float* ele_t = (const float*)d_in[4];
    const float* azi_t = (const float*)d_in[5];
    const float* Wq    = (const float*)d_in[6];
    const float* bq    = (const float*)d_in[7];
    const float* Wk    = (const float*)d_in[8];
    const float* bk    = (const float*)d_in[9];
    const float* Wv    = (const float*)d_in[10];
    const float* bv    = (const float*)d_in[11];
    float* out = (float*)d_out;

    const int proj_smem = P_WORDS * (int)sizeof(float);

    cudaFuncSetAttribute(proj_kernel, cudaFuncAttributeMaxDynamicSharedMemorySize, proj_smem);
    cudaFuncSetAttribute(attn_kernel, cudaFuncAttributeMaxDynamicSharedMemorySize, SM_ATTN);

    proj_kernel<<<NTOT / PROJ_ROWS, PROJ_THREADS, proj_smem>>>(
        pv, ele, azi, ele_t, azi_t, Wq, bq, Wk, bk, Wv, bv);
    attn_kernel<<<NRANGES, ATTN_THREADS, SM_ATTN>>>(out);
}